// round 1
// baseline (speedup 1.0000x reference)
#include <cuda_runtime.h>

// LogicDense: out[i][j] = c0 + c1*a + c2*b + c3*a*b
//   a = x[i, idx0[j]], b = x[i, idx1[j]]
//   (c0..c3) = softmax(weight[j]) @ T   (T = 16x4 LUT coefficient table)
//
// Strategy:
//   1. detect_kernel: figure out whether indices are int64 or int32 (JAX x64 ambiguity).
//   2. precompute_kernel: per output column, softmax+coeff fold and premultiplied
//      shared-memory offsets, packed into __device__ tables (read coalesced later).
//   3. main_kernel: each block stages ROWS=8 rows of x TRANSPOSED in shared memory
//      with a 12-float (48B) stride so that the two float4 gathers per column hit
//      all 32 banks; computes 8 outputs per (thread, column) with 3 FMAs each and
//      writes coalesced.

#define ROWS 8
#define RS   12           // shared-memory stride (floats) per x element
#define MAX_OUT 16384

__device__ float4 g_coef[MAX_OUT];
__device__ int2   g_off[MAX_OUT];
__device__ int    g_is64;

// difflogic bin_op_s coefficient table: op_k(a,b) = t0 + t1*a + t2*b + t3*ab
__constant__ float c_T[64] = {
    0.f, 0.f, 0.f, 0.f,
    0.f, 0.f, 0.f, 1.f,
    0.f, 1.f, 0.f,-1.f,
    0.f, 1.f, 0.f, 0.f,
    0.f, 0.f, 1.f,-1.f,
    0.f, 0.f, 1.f, 0.f,
    0.f, 1.f, 1.f,-2.f,
    0.f, 1.f, 1.f,-1.f,
    1.f,-1.f,-1.f, 1.f,
    1.f,-1.f,-1.f, 2.f,
    1.f, 0.f,-1.f, 0.f,
    1.f, 0.f,-1.f, 1.f,
    1.f,-1.f, 0.f, 0.f,
    1.f,-1.f, 0.f, 1.f,
    1.f, 0.f, 0.f,-1.f,
    1.f, 0.f, 0.f, 0.f
};

// One block. ORs all odd 32-bit words of the index buffer over the range that is
// valid under BOTH dtype interpretations (2*out_dim u32 words). If indices are
// int64 (values < in_dim), every odd word is a zero high-word -> OR == 0.
// If int32, odd words are random indices -> OR != 0 (P[all zero] ~ 0).
__global__ void detect_kernel(const unsigned int* __restrict__ u, int n_u32) {
    __shared__ unsigned int red[256];
    unsigned int v = 0;
    for (int k = 1 + 2 * (int)threadIdx.x; k < n_u32; k += 2 * (int)blockDim.x)
        v |= u[k];
    red[threadIdx.x] = v;
    __syncthreads();
    for (int s = 128; s > 0; s >>= 1) {
        if ((int)threadIdx.x < s) red[threadIdx.x] |= red[threadIdx.x + s];
        __syncthreads();
    }
    if (threadIdx.x == 0) g_is64 = (red[0] == 0u) ? 1 : 0;
}

__global__ void precompute_kernel(const void* __restrict__ idx_raw,
                                  const float* __restrict__ w,
                                  int out_dim) {
    int j = blockIdx.x * blockDim.x + threadIdx.x;
    if (j >= out_dim) return;

    float wv[16];
    float m = -1e30f;
#pragma unroll
    for (int k = 0; k < 16; k++) {
        wv[k] = w[j * 16 + k];
        m = fmaxf(m, wv[k]);
    }
    float s = 0.f;
#pragma unroll
    for (int k = 0; k < 16; k++) {
        wv[k] = __expf(wv[k] - m);
        s += wv[k];
    }
    float inv = 1.f / s;
    float c0 = 0.f, c1 = 0.f, c2 = 0.f, c3 = 0.f;
#pragma unroll
    for (int k = 0; k < 16; k++) {
        float p = wv[k] * inv;
        c0 = fmaf(p, c_T[4 * k + 0], c0);
        c1 = fmaf(p, c_T[4 * k + 1], c1);
        c2 = fmaf(p, c_T[4 * k + 2], c2);
        c3 = fmaf(p, c_T[4 * k + 3], c3);
    }
    g_coef[j] = make_float4(c0, c1, c2, c3);

    int i0, i1;
    if (g_is64) {
        const long long* p = (const long long*)idx_raw;
        i0 = (int)p[j];
        i1 = (int)p[out_dim + j];
    } else {
        const int* p = (const int*)idx_raw;
        i0 = p[j];
        i1 = p[out_dim + j];
    }
    g_off[j] = make_int2(i0 * RS, i1 * RS);
}

template <bool FULL>
__global__ __launch_bounds__(1024, 1) void logic_main_kernel(
    const float* __restrict__ x,
    float* __restrict__ out,
    int in_dim, int out_dim, int batch) {
    extern __shared__ float sx[];   // in_dim * RS floats

    const int rb = blockIdx.x * ROWS;
    const int nr = FULL ? ROWS : min(ROWS, batch - rb);

    // ---- stage ROWS rows of x, transposed, stride RS ----
    if (FULL && (in_dim & 3) == 0) {
#pragma unroll
        for (int r = 0; r < ROWS; r++) {
            const float4* xr = (const float4*)(x + (size_t)(rb + r) * in_dim);
            const int n4 = in_dim >> 2;
            for (int i = threadIdx.x; i < n4; i += blockDim.x) {
                float4 v = xr[i];
                int base = (i << 2) * RS + r;
                sx[base]          = v.x;
                sx[base + RS]     = v.y;
                sx[base + 2 * RS] = v.z;
                sx[base + 3 * RS] = v.w;
            }
        }
    } else {
        for (int r = 0; r < nr; r++) {
            const float* xr = x + (size_t)(rb + r) * in_dim;
            for (int i = threadIdx.x; i < in_dim; i += blockDim.x)
                sx[i * RS + r] = xr[i];
        }
    }
    __syncthreads();

    // ---- compute: each thread walks columns; 8 rows per column via float4 gathers ----
    for (int j = threadIdx.x; j < out_dim; j += blockDim.x) {
        float4 c = g_coef[j];
        int2 o = g_off[j];

        float4 aLo = *(const float4*)(sx + o.x);
        float4 aHi = *(const float4*)(sx + o.x + 4);
        float4 bLo = *(const float4*)(sx + o.y);
        float4 bHi = *(const float4*)(sx + o.y + 4);

        float va[ROWS] = {aLo.x, aLo.y, aLo.z, aLo.w, aHi.x, aHi.y, aHi.z, aHi.w};
        float vb[ROWS] = {bLo.x, bLo.y, bLo.z, bLo.w, bHi.x, bHi.y, bHi.z, bHi.w};

        float* op = out + (size_t)rb * out_dim + j;
#pragma unroll
        for (int r = 0; r < ROWS; r++) {
            if (FULL || r < nr) {
                // c0 + c1*a + c2*b + c3*a*b = a*(c1 + c3*b) + (c0 + c2*b)
                float res = fmaf(va[r], fmaf(vb[r], c.w, c.y),
                                 fmaf(vb[r], c.z, c.x));
                op[(size_t)r * out_dim] = res;
            }
        }
    }
}

extern "C" void kernel_launch(void* const* d_in, const int* in_sizes, int n_in,
                              void* d_out, int out_size) {
    const float* x   = (const float*)d_in[0];
    const void*  idx = d_in[1];
    const float* w   = (const float*)d_in[2];
    float*       out = (float*)d_out;

    const int out_dim = in_sizes[2] / 16;         // weight is (out_dim, 16)
    const int batch   = out_size / out_dim;       // out is (batch, out_dim)
    const int in_dim  = in_sizes[0] / batch;      // x is (batch, in_dim)

    // 1) dtype detection for indices (int64 vs int32)
    detect_kernel<<<1, 256>>>((const unsigned int*)idx, 2 * out_dim);

    // 2) per-column coefficient + offset table
    precompute_kernel<<<(out_dim + 255) / 256, 256>>>(idx, w, out_dim);

    // 3) main fused gather+poly kernel
    const size_t smem = (size_t)in_dim * RS * sizeof(float);   // 192 KiB @ in_dim=4096
    const int grid = (batch + ROWS - 1) / ROWS;

    if (batch % ROWS == 0) {
        cudaFuncSetAttribute(logic_main_kernel<true>,
                             cudaFuncAttributeMaxDynamicSharedMemorySize, (int)smem);
        logic_main_kernel<true><<<grid, 1024, smem>>>(x, out, in_dim, out_dim, batch);
    } else {
        cudaFuncSetAttribute(logic_main_kernel<false>,
                             cudaFuncAttributeMaxDynamicSharedMemorySize, (int)smem);
        logic_main_kernel<false><<<grid, 1024, smem>>>(x, out, in_dim, out_dim, batch);
    }
}

// round 2
// speedup vs baseline: 1.4501x; 1.4501x over previous
#include <cuda_runtime.h>

// LogicDense: out[i][j] = c0 + c1*a + c2*b + c3*a*b
//   a = x[i, idx0[j]], b = x[i, idx1[j]]
//   (c0..c3) = softmax(weight[j]) @ T
//
// R2 changes vs R1 (92 us):
//  - Transposed smem layout stride 12 -> stride 8 + XOR swizzle
//    f(idx,r) = (8*idx + r) ^ (((idx>>2)&7)<<2).
//    Staging stores: 16-way bank conflict -> 4-way (balanced min).
//    Gathers unchanged: float4 at lo (rows 0-3) and lo^4 (rows 4-7),
//    swizzled offsets precomputed into the column table.
//  - detect_kernel folded into precompute (each block re-derives the
//    int64/int32 flag from the first odd u32 words; L2-resident).
//  - smem 192 KiB -> 128 KiB.

#define ROWS 8
#define MAX_OUT 16384

__device__ float4 g_coef[MAX_OUT];
__device__ int2   g_off[MAX_OUT];

// difflogic bin_op_s coefficient table: op_k(a,b) = t0 + t1*a + t2*b + t3*ab
__constant__ float c_T[64] = {
    0.f, 0.f, 0.f, 0.f,
    0.f, 0.f, 0.f, 1.f,
    0.f, 1.f, 0.f,-1.f,
    0.f, 1.f, 0.f, 0.f,
    0.f, 0.f, 1.f,-1.f,
    0.f, 0.f, 1.f, 0.f,
    0.f, 1.f, 1.f,-2.f,
    0.f, 1.f, 1.f,-1.f,
    1.f,-1.f,-1.f, 1.f,
    1.f,-1.f,-1.f, 2.f,
    1.f, 0.f,-1.f, 0.f,
    1.f, 0.f,-1.f, 1.f,
    1.f,-1.f, 0.f, 0.f,
    1.f,-1.f, 0.f, 1.f,
    1.f, 0.f, 0.f,-1.f,
    1.f, 0.f, 0.f, 0.f
};

__device__ __forceinline__ int swz_off(int idx) {
    // float-index of rows 0-3 of element idx in the swizzled transposed tile
    return (idx << 3) ^ (((idx >> 2) & 7) << 2);
}

// Precompute per-column coefficients + swizzled gather offsets.
// Index dtype (int64 vs int32) is detected per-block: OR of the odd 32-bit
// words over the first n_chk words is zero iff the words are int64 high words
// (indices < in_dim). Those 8 KiB are L2-resident after the first block.
__global__ void precompute_kernel(const void* __restrict__ idx_raw,
                                  const float* __restrict__ w,
                                  int out_dim) {
    __shared__ unsigned int red[256];
    __shared__ int s_is64;

    const unsigned int* u = (const unsigned int*)idx_raw;
    int n_chk = 2 * out_dim;                 // valid under both interpretations
    if (n_chk > 4096) n_chk = 4096;
    unsigned int v = 0;
    for (int k = 1 + 2 * (int)threadIdx.x; k < n_chk; k += 2 * (int)blockDim.x)
        v |= u[k];
    red[threadIdx.x] = v;
    __syncthreads();
    for (int s = 128; s > 0; s >>= 1) {
        if ((int)threadIdx.x < s) red[threadIdx.x] |= red[threadIdx.x + s];
        __syncthreads();
    }
    if (threadIdx.x == 0) s_is64 = (red[0] == 0u) ? 1 : 0;
    __syncthreads();
    const int is64 = s_is64;

    int j = blockIdx.x * blockDim.x + threadIdx.x;
    if (j >= out_dim) return;

    float wv[16];
    float m = -1e30f;
#pragma unroll
    for (int k = 0; k < 16; k++) {
        wv[k] = w[j * 16 + k];
        m = fmaxf(m, wv[k]);
    }
    float s = 0.f;
#pragma unroll
    for (int k = 0; k < 16; k++) {
        wv[k] = __expf(wv[k] - m);
        s += wv[k];
    }
    float inv = 1.f / s;
    float c0 = 0.f, c1 = 0.f, c2 = 0.f, c3 = 0.f;
#pragma unroll
    for (int k = 0; k < 16; k++) {
        float p = wv[k] * inv;
        c0 = fmaf(p, c_T[4 * k + 0], c0);
        c1 = fmaf(p, c_T[4 * k + 1], c1);
        c2 = fmaf(p, c_T[4 * k + 2], c2);
        c3 = fmaf(p, c_T[4 * k + 3], c3);
    }
    g_coef[j] = make_float4(c0, c1, c2, c3);

    int i0, i1;
    if (is64) {
        const long long* p = (const long long*)idx_raw;
        i0 = (int)p[j];
        i1 = (int)p[out_dim + j];
    } else {
        const int* p = (const int*)idx_raw;
        i0 = p[j];
        i1 = p[out_dim + j];
    }
    g_off[j] = make_int2(swz_off(i0), swz_off(i1));
}

template <bool FULL>
__global__ __launch_bounds__(1024, 1) void logic_main_kernel(
    const float* __restrict__ x,
    float* __restrict__ out,
    int in_dim, int out_dim, int batch) {
    extern __shared__ float sx[];   // in_dim * 8 floats, swizzled transposed

    const int rb = blockIdx.x * ROWS;
    const int nr = FULL ? ROWS : min(ROWS, batch - rb);

    // ---- stage ROWS rows of x, transposed + swizzled ----
    const int n4 = in_dim >> 2;
    for (int i = threadIdx.x; i < n4; i += blockDim.x) {
        const int t = (i & 7) << 2;
        const int base = i << 5;   // 32*i
#pragma unroll
        for (int r = 0; r < ROWS; r++) {
            float4 v;
            if (FULL || r < nr)
                v = *(const float4*)(x + (size_t)(rb + r) * in_dim + (i << 2));
            else
                v = make_float4(0.f, 0.f, 0.f, 0.f);
            sx[(base + r)      ^ t] = v.x;
            sx[(base + 8 + r)  ^ t] = v.y;
            sx[(base + 16 + r) ^ t] = v.z;
            sx[(base + 24 + r) ^ t] = v.w;
        }
    }
    __syncthreads();

    // ---- compute: per column, two float4 gathers per operand ----
    for (int j = threadIdx.x; j < out_dim; j += blockDim.x) {
        const float4 c = g_coef[j];
        const int2 o = g_off[j];

        const float4 aLo = *(const float4*)(sx + o.x);
        const float4 aHi = *(const float4*)(sx + (o.x ^ 4));
        const float4 bLo = *(const float4*)(sx + o.y);
        const float4 bHi = *(const float4*)(sx + (o.y ^ 4));

        const float va[ROWS] = {aLo.x, aLo.y, aLo.z, aLo.w, aHi.x, aHi.y, aHi.z, aHi.w};
        const float vb[ROWS] = {bLo.x, bLo.y, bLo.z, bLo.w, bHi.x, bHi.y, bHi.z, bHi.w};

        float* op = out + (size_t)rb * out_dim + j;
#pragma unroll
        for (int r = 0; r < ROWS; r++) {
            if (FULL || r < nr) {
                // c0 + c1*a + c2*b + c3*a*b = a*(c1 + c3*b) + (c0 + c2*b)
                float res = fmaf(va[r], fmaf(vb[r], c.w, c.y),
                                 fmaf(vb[r], c.z, c.x));
                op[(size_t)r * out_dim] = res;
            }
        }
    }
}

extern "C" void kernel_launch(void* const* d_in, const int* in_sizes, int n_in,
                              void* d_out, int out_size) {
    const float* x   = (const float*)d_in[0];
    const void*  idx = d_in[1];
    const float* w   = (const float*)d_in[2];
    float*       out = (float*)d_out;

    const int out_dim = in_sizes[2] / 16;         // weight is (out_dim, 16)
    const int batch   = out_size / out_dim;       // out is (batch, out_dim)
    const int in_dim  = in_sizes[0] / batch;      // x is (batch, in_dim)

    // 1) per-column coefficient + swizzled offset table (dtype detect folded in)
    precompute_kernel<<<(out_dim + 255) / 256, 256>>>(idx, w, out_dim);

    // 2) main fused gather+poly kernel
    const size_t smem = (size_t)in_dim * ROWS * sizeof(float);   // 128 KiB @ 4096
    const int grid = (batch + ROWS - 1) / ROWS;

    if (batch % ROWS == 0) {
        cudaFuncSetAttribute(logic_main_kernel<true>,
                             cudaFuncAttributeMaxDynamicSharedMemorySize, (int)smem);
        logic_main_kernel<true><<<grid, 1024, smem>>>(x, out, in_dim, out_dim, batch);
    } else {
        cudaFuncSetAttribute(logic_main_kernel<false>,
                             cudaFuncAttributeMaxDynamicSharedMemorySize, (int)smem);
        logic_main_kernel<false><<<grid, 1024, smem>>>(x, out, in_dim, out_dim, batch);
    }
}

// round 3
// speedup vs baseline: 1.5501x; 1.0690x over previous
#include <cuda_runtime.h>

// LogicDense: out[i][j] = c0 + c1*a + c2*b + c3*a*b
//   a = x[i, idx0[j]], b = x[i, idx1[j]]
//   (c0..c3) = softmax(weight[j]) @ T
//
// R3 changes vs R2 (63.5 us, main kernel L1-bound at 67%):
//  - ROWS 8 -> 4: the per-element transposed group is exactly a float4, so
//    staging is an in-register 4x4 transpose + STS.128 (4 phases / 512B =
//    crossbar floor, no conflict waste; was 4-way-conflicted scalar STS).
//  - Gather: 1 LDS.128 per operand (was 2).
//  - smem 128 KiB -> 64 KiB: 2-3 blocks/SM, staging of one block overlaps
//    compute of another (fixes issue=23.7%).
//  - Offsets packed 2 x u16 into one uint -> 20B/column table traffic.

#define ROWS 4
#define MAX_OUT 16384

__device__ float4       g_coef[MAX_OUT];
__device__ unsigned int g_po[MAX_OUT];    // packed swizzled offsets: lo|hi<<16

// difflogic bin_op_s coefficient table: op_k(a,b) = t0 + t1*a + t2*b + t3*ab
__constant__ float c_T[64] = {
    0.f, 0.f, 0.f, 0.f,
    0.f, 0.f, 0.f, 1.f,
    0.f, 1.f, 0.f,-1.f,
    0.f, 1.f, 0.f, 0.f,
    0.f, 0.f, 1.f,-1.f,
    0.f, 0.f, 1.f, 0.f,
    0.f, 1.f, 1.f,-2.f,
    0.f, 1.f, 1.f,-1.f,
    1.f,-1.f,-1.f, 1.f,
    1.f,-1.f,-1.f, 2.f,
    1.f, 0.f,-1.f, 0.f,
    1.f, 0.f,-1.f, 1.f,
    1.f,-1.f, 0.f, 0.f,
    1.f,-1.f, 0.f, 1.f,
    1.f, 0.f, 0.f,-1.f,
    1.f, 0.f, 0.f, 0.f
};

__device__ __forceinline__ int swz_off(int idx) {
    // float-index of the 4-row group of element idx in the swizzled tile
    return (idx << 2) ^ (((idx >> 3) & 7) << 2);
}

// Per-column coefficients + packed swizzled gather offsets.
// Index dtype (int64 vs int32) detected per-block: OR of odd u32 words over
// the first n_chk words is zero iff they are int64 high words.
__global__ void precompute_kernel(const void* __restrict__ idx_raw,
                                  const float* __restrict__ w,
                                  int out_dim) {
    __shared__ unsigned int red[128];
    __shared__ int s_is64;

    const unsigned int* u = (const unsigned int*)idx_raw;
    int n_chk = 2 * out_dim;
    if (n_chk > 512) n_chk = 512;
    unsigned int v = 0;
    for (int k = 1 + 2 * (int)threadIdx.x; k < n_chk; k += 2 * (int)blockDim.x)
        v |= u[k];
    red[threadIdx.x] = v;
    __syncthreads();
    for (int s = 64; s > 0; s >>= 1) {
        if ((int)threadIdx.x < s) red[threadIdx.x] |= red[threadIdx.x + s];
        __syncthreads();
    }
    if (threadIdx.x == 0) s_is64 = (red[0] == 0u) ? 1 : 0;
    __syncthreads();
    const int is64 = s_is64;

    int j = blockIdx.x * blockDim.x + threadIdx.x;
    if (j >= out_dim) return;

    float wv[16];
    float m = -1e30f;
#pragma unroll
    for (int k = 0; k < 16; k++) {
        wv[k] = w[j * 16 + k];
        m = fmaxf(m, wv[k]);
    }
    float s = 0.f;
#pragma unroll
    for (int k = 0; k < 16; k++) {
        wv[k] = __expf(wv[k] - m);
        s += wv[k];
    }
    float inv = 1.f / s;
    float c0 = 0.f, c1 = 0.f, c2 = 0.f, c3 = 0.f;
#pragma unroll
    for (int k = 0; k < 16; k++) {
        float p = wv[k] * inv;
        c0 = fmaf(p, c_T[4 * k + 0], c0);
        c1 = fmaf(p, c_T[4 * k + 1], c1);
        c2 = fmaf(p, c_T[4 * k + 2], c2);
        c3 = fmaf(p, c_T[4 * k + 3], c3);
    }
    g_coef[j] = make_float4(c0, c1, c2, c3);

    int i0, i1;
    if (is64) {
        const long long* p = (const long long*)idx_raw;
        i0 = (int)p[j];
        i1 = (int)p[out_dim + j];
    } else {
        const int* p = (const int*)idx_raw;
        i0 = p[j];
        i1 = p[out_dim + j];
    }
    g_po[j] = (unsigned int)swz_off(i0) | ((unsigned int)swz_off(i1) << 16);
}

template <bool FULL>
__global__ __launch_bounds__(512, 3) void logic_main_kernel(
    const float* __restrict__ x,
    float* __restrict__ out,
    int in_dim, int out_dim, int batch) {
    extern __shared__ float sx[];   // in_dim * 4 floats, swizzled transposed

    const int rb = blockIdx.x * ROWS;
    const int nr = FULL ? ROWS : min(ROWS, batch - rb);

    // ---- stage 4 rows of x: LDG.128 x4, in-register 4x4 transpose, STS.128 ----
    {
        const int n4 = in_dim >> 2;
        const float4* x0 = (const float4*)(x + (size_t)(rb + 0) * in_dim);
        const float4* x1 = (const float4*)(x + (size_t)(rb + (FULL || nr > 1 ? 1 : 0)) * in_dim);
        const float4* x2 = (const float4*)(x + (size_t)(rb + (FULL || nr > 2 ? 2 : 0)) * in_dim);
        const float4* x3 = (const float4*)(x + (size_t)(rb + (FULL || nr > 3 ? 3 : 0)) * in_dim);
        for (int i = threadIdx.x; i < n4; i += blockDim.x) {
            float4 r0 = x0[i];
            float4 r1 = x1[i];
            float4 r2 = x2[i];
            float4 r3 = x3[i];
            const int t = ((i >> 1) & 7) << 2;
            const int base = i << 4;   // 16*i
            *(float4*)(sx + ((base     ) ^ t)) = make_float4(r0.x, r1.x, r2.x, r3.x);
            *(float4*)(sx + ((base +  4) ^ t)) = make_float4(r0.y, r1.y, r2.y, r3.y);
            *(float4*)(sx + ((base +  8) ^ t)) = make_float4(r0.z, r1.z, r2.z, r3.z);
            *(float4*)(sx + ((base + 12) ^ t)) = make_float4(r0.w, r1.w, r2.w, r3.w);
        }
    }
    __syncthreads();

    // ---- compute: per column, one float4 gather per operand ----
    for (int j = threadIdx.x; j < out_dim; j += blockDim.x) {
        const float4 c = g_coef[j];
        const unsigned int po = g_po[j];

        const float4 a = *(const float4*)(sx + (po & 0xFFFFu));
        const float4 b = *(const float4*)(sx + (po >> 16));

        float* op = out + (size_t)rb * out_dim + j;
        // c0 + c1*a + c2*b + c3*a*b = a*(c1 + c3*b) + (c0 + c2*b)
        if (FULL || nr > 0)
            op[0] = fmaf(a.x, fmaf(b.x, c.w, c.y), fmaf(b.x, c.z, c.x));
        if (FULL || nr > 1)
            op[(size_t)out_dim] = fmaf(a.y, fmaf(b.y, c.w, c.y), fmaf(b.y, c.z, c.x));
        if (FULL || nr > 2)
            op[(size_t)2 * out_dim] = fmaf(a.z, fmaf(b.z, c.w, c.y), fmaf(b.z, c.z, c.x));
        if (FULL || nr > 3)
            op[(size_t)3 * out_dim] = fmaf(a.w, fmaf(b.w, c.w, c.y), fmaf(b.w, c.z, c.x));
    }
}

extern "C" void kernel_launch(void* const* d_in, const int* in_sizes, int n_in,
                              void* d_out, int out_size) {
    const float* x   = (const float*)d_in[0];
    const void*  idx = d_in[1];
    const float* w   = (const float*)d_in[2];
    float*       out = (float*)d_out;

    const int out_dim = in_sizes[2] / 16;         // weight is (out_dim, 16)
    const int batch   = out_size / out_dim;       // out is (batch, out_dim)
    const int in_dim  = in_sizes[0] / batch;      // x is (batch, in_dim)

    // 1) per-column coefficient + packed swizzled offsets (dtype detect folded in)
    precompute_kernel<<<(out_dim + 127) / 128, 128>>>(idx, w, out_dim);

    // 2) main fused gather+poly kernel
    const size_t smem = (size_t)in_dim * ROWS * sizeof(float);   // 64 KiB @ 4096
    const int grid = (batch + ROWS - 1) / ROWS;

    if (batch % ROWS == 0) {
        cudaFuncSetAttribute(logic_main_kernel<true>,
                             cudaFuncAttributeMaxDynamicSharedMemorySize, (int)smem);
        logic_main_kernel<true><<<grid, 512, smem>>>(x, out, in_dim, out_dim, batch);
    } else {
        cudaFuncSetAttribute(logic_main_kernel<false>,
                             cudaFuncAttributeMaxDynamicSharedMemorySize, (int)smem);
        logic_main_kernel<false><<<grid, 512, smem>>>(x, out, in_dim, out_dim, batch);
    }
}

// round 4
// speedup vs baseline: 1.6554x; 1.0679x over previous
#include <cuda_runtime.h>
#include <cuda_fp16.h>

// LogicDense: out[i][j] = c0 + c1*a + c2*b + c3*a*b
//   a = x[i, idx0[j]], b = x[i, idx1[j]]
//
// R4 vs R3 (59.4 us, main kernel L1-bound, gathers+coef = 75% of wavefronts):
//  - Staged tile in FP16: 8 rows x 2B = 16B per element -> ONE LDS.128 gather
//    serves 8 outputs (was: one per 4). Gather wavefronts per output halved.
//  - ROWS 4 -> 8: coef/po table traffic per output halved.
//  - Tile stays 64 KiB (in_dim * 8 * half) -> 3 blocks/SM preserved.
//  - Swizzle (idx<<3) ^ (((idx>>3)&7)<<3) in half units: staging STS.128 cycles
//    all 8 crossbar quads (4-phase floor); gathers keep random-conflict stats.
//  - Math still fp32 (convert on gather); x->half rounding rel err ~1e-4 << 1e-3.

#define ROWS 8
#define MAX_OUT 16384

__device__ float4       g_coef[MAX_OUT];
__device__ unsigned int g_po[MAX_OUT];    // packed swizzled half-offsets: lo | hi<<16

__constant__ float c_T[64] = {
    0.f, 0.f, 0.f, 0.f,
    0.f, 0.f, 0.f, 1.f,
    0.f, 1.f, 0.f,-1.f,
    0.f, 1.f, 0.f, 0.f,
    0.f, 0.f, 1.f,-1.f,
    0.f, 0.f, 1.f, 0.f,
    0.f, 1.f, 1.f,-2.f,
    0.f, 1.f, 1.f,-1.f,
    1.f,-1.f,-1.f, 1.f,
    1.f,-1.f,-1.f, 2.f,
    1.f, 0.f,-1.f, 0.f,
    1.f, 0.f,-1.f, 1.f,
    1.f,-1.f, 0.f, 0.f,
    1.f,-1.f, 0.f, 1.f,
    1.f, 0.f, 0.f,-1.f,
    1.f, 0.f, 0.f, 0.f
};

__device__ __forceinline__ int swz_off(int idx) {
    // half-index of the 8-row group of element idx in the swizzled tile
    return (idx << 3) ^ (((idx >> 3) & 7) << 3);
}

__global__ void precompute_kernel(const void* __restrict__ idx_raw,
                                  const float* __restrict__ w,
                                  int out_dim) {
    __shared__ unsigned int red[128];
    __shared__ int s_is64;

    // int64-vs-int32 detection: OR of odd u32 words == 0 iff int64 high words.
    const unsigned int* u = (const unsigned int*)idx_raw;
    int n_chk = 2 * out_dim;
    if (n_chk > 512) n_chk = 512;
    unsigned int v = 0;
    for (int k = 1 + 2 * (int)threadIdx.x; k < n_chk; k += 2 * (int)blockDim.x)
        v |= u[k];
    red[threadIdx.x] = v;
    __syncthreads();
    for (int s = 64; s > 0; s >>= 1) {
        if ((int)threadIdx.x < s) red[threadIdx.x] |= red[threadIdx.x + s];
        __syncthreads();
    }
    if (threadIdx.x == 0) s_is64 = (red[0] == 0u) ? 1 : 0;
    __syncthreads();
    const int is64 = s_is64;

    int j = blockIdx.x * blockDim.x + threadIdx.x;
    if (j >= out_dim) return;

    float wv[16];
    float m = -1e30f;
#pragma unroll
    for (int k = 0; k < 16; k++) {
        wv[k] = w[j * 16 + k];
        m = fmaxf(m, wv[k]);
    }
    float s = 0.f;
#pragma unroll
    for (int k = 0; k < 16; k++) {
        wv[k] = __expf(wv[k] - m);
        s += wv[k];
    }
    float inv = 1.f / s;
    float c0 = 0.f, c1 = 0.f, c2 = 0.f, c3 = 0.f;
#pragma unroll
    for (int k = 0; k < 16; k++) {
        float p = wv[k] * inv;
        c0 = fmaf(p, c_T[4 * k + 0], c0);
        c1 = fmaf(p, c_T[4 * k + 1], c1);
        c2 = fmaf(p, c_T[4 * k + 2], c2);
        c3 = fmaf(p, c_T[4 * k + 3], c3);
    }
    g_coef[j] = make_float4(c0, c1, c2, c3);

    int i0, i1;
    if (is64) {
        const long long* p = (const long long*)idx_raw;
        i0 = (int)p[j];
        i1 = (int)p[out_dim + j];
    } else {
        const int* p = (const int*)idx_raw;
        i0 = p[j];
        i1 = p[out_dim + j];
    }
    g_po[j] = (unsigned int)swz_off(i0) | ((unsigned int)swz_off(i1) << 16);
}

__device__ __forceinline__ unsigned int pack_h2(float lo, float hi) {
    __half2 h = __floats2half2_rn(lo, hi);
    return *(unsigned int*)&h;
}

template <bool FULL>
__global__ __launch_bounds__(512, 3) void logic_main_kernel(
    const float* __restrict__ x,
    float* __restrict__ out,
    int in_dim, int out_dim, int batch) {
    extern __shared__ __half sh[];   // in_dim * 8 halfs (64 KiB @ 4096), swizzled

    const int rb = blockIdx.x * ROWS;
    const int nr = FULL ? ROWS : min(ROWS, batch - rb);

    // ---- stage 8 rows: LDG.128 x8, convert to half, repack, STS.128 x4 ----
    {
        const int n4 = in_dim >> 2;   // element-chunks of 4
        const float* xb = x + (size_t)rb * in_dim;
        for (int i = threadIdx.x; i < n4; i += blockDim.x) {
            float4 r[ROWS];
#pragma unroll
            for (int rr = 0; rr < ROWS; rr++) {
                int row = (FULL || rr < nr) ? rr : 0;
                r[rr] = *(const float4*)(xb + (size_t)row * in_dim + (i << 2));
            }
#pragma unroll
            for (int k = 0; k < 4; k++) {
                const float* e = &r[0].x;   // r is contiguous float array
                uint4 pk;
                pk.x = pack_h2(((const float4*)e)[0].x * 0.f + (&r[0].x)[k],
                               (&r[1].x)[k]);
                pk.y = pack_h2((&r[2].x)[k], (&r[3].x)[k]);
                pk.z = pack_h2((&r[4].x)[k], (&r[5].x)[k]);
                pk.w = pack_h2((&r[6].x)[k], (&r[7].x)[k]);
                const int idx = (i << 2) + k;
                *(uint4*)(sh + swz_off(idx)) = pk;
            }
        }
    }
    __syncthreads();

    // ---- compute: one LDS.128 per operand serves all 8 rows ----
    for (int j = threadIdx.x; j < out_dim; j += blockDim.x) {
        const float4 c = g_coef[j];
        const unsigned int po = g_po[j];

        const uint4 ap = *(const uint4*)(sh + (po & 0xFFFFu));
        const uint4 bp = *(const uint4*)(sh + (po >> 16));

        float2 a01 = __half22float2(*(const __half2*)&ap.x);
        float2 a23 = __half22float2(*(const __half2*)&ap.y);
        float2 a45 = __half22float2(*(const __half2*)&ap.z);
        float2 a67 = __half22float2(*(const __half2*)&ap.w);
        float2 b01 = __half22float2(*(const __half2*)&bp.x);
        float2 b23 = __half22float2(*(const __half2*)&bp.y);
        float2 b45 = __half22float2(*(const __half2*)&bp.z);
        float2 b67 = __half22float2(*(const __half2*)&bp.w);

        const float va[ROWS] = {a01.x, a01.y, a23.x, a23.y, a45.x, a45.y, a67.x, a67.y};
        const float vb[ROWS] = {b01.x, b01.y, b23.x, b23.y, b45.x, b45.y, b67.x, b67.y};

        float* op = out + (size_t)rb * out_dim + j;
#pragma unroll
        for (int r = 0; r < ROWS; r++) {
            if (FULL || r < nr) {
                // c0 + c1*a + c2*b + c3*a*b = a*(c1 + c3*b) + (c0 + c2*b)
                float res = fmaf(va[r], fmaf(vb[r], c.w, c.y),
                                 fmaf(vb[r], c.z, c.x));
                op[(size_t)r * out_dim] = res;
            }
        }
    }
}

extern "C" void kernel_launch(void* const* d_in, const int* in_sizes, int n_in,
                              void* d_out, int out_size) {
    const float* x   = (const float*)d_in[0];
    const void*  idx = d_in[1];
    const float* w   = (const float*)d_in[2];
    float*       out = (float*)d_out;

    const int out_dim = in_sizes[2] / 16;         // weight is (out_dim, 16)
    const int batch   = out_size / out_dim;       // out is (batch, out_dim)
    const int in_dim  = in_sizes[0] / batch;      // x is (batch, in_dim)

    precompute_kernel<<<(out_dim + 127) / 128, 128>>>(idx, w, out_dim);

    const size_t smem = (size_t)in_dim * ROWS * sizeof(__half);   // 64 KiB @ 4096
    const int grid = (batch + ROWS - 1) / ROWS;

    if (batch % ROWS == 0) {
        cudaFuncSetAttribute(logic_main_kernel<true>,
                             cudaFuncAttributeMaxDynamicSharedMemorySize, (int)smem);
        logic_main_kernel<true><<<grid, 512, smem>>>(x, out, in_dim, out_dim, batch);
    } else {
        cudaFuncSetAttribute(logic_main_kernel<false>,
                             cudaFuncAttributeMaxDynamicSharedMemorySize, (int)smem);
        logic_main_kernel<false><<<grid, 512, smem>>>(x, out, in_dim, out_dim, batch);
    }
}